// round 6
// baseline (speedup 1.0000x reference)
#include <cuda_runtime.h>

#define NB 256
#define NT 1024
#define NV 5000
#define ND 100
#define NH 64
#define NC 2

// Scratch: EW = E @ W + b, [V, H]. 1.28 MB -> fully L2-resident.
__device__ float g_EWb[NV * NH];

// ---------------------------------------------------------------------------
// Kernel A: EWb[v][j] = sum_d E[v][d] * W[d][j] + b[j]
// ---------------------------------------------------------------------------
__global__ void ew_kernel(const float* __restrict__ E,
                          const float* __restrict__ W,
                          const float* __restrict__ bias) {
    int v = blockIdx.x * 4 + (threadIdx.x >> 6);
    int j = threadIdx.x & 63;
    if (v >= NV) return;
    float acc = bias[j];
    const float* e = E + v * ND;
    #pragma unroll 4
    for (int d = 0; d < ND; d++)
        acc = fmaf(e[d], W[d * NH + j], acc);
    g_EWb[v * NH + j] = acc;
}

// HW tanh (MUFU.TANH): lat 16, single instruction, ~2^-11 error.
__device__ __forceinline__ float tanh_fast(float x) {
    float y;
    asm("tanh.approx.f32 %0, %1;" : "=f"(y) : "f"(x));
    return y;
}

// ---------------------------------------------------------------------------
// Kernel B: masked tanh RNN, T=1024 steps + mean-pool + dense + sigmoid.
// ONE BLOCK (128 threads = 4 warps) PER ROW. K-split by 2 in-warp: lanes
// (l, l+16) of warp w own output j = 16w + (l&15); lane's K-half = l>>4.
// SCALAR FFMA ONLY (f32x2 regressed twice: RF-bank floor >= 3 on 64-bit
// triple-operand FMA beats its 2x width). 32 FFMA + 8 LDS.128 per thread;
// halves merge with one shfl.bfly(16). ew is folded into accumulator a0
// (low lanes only; partner receives it via the shfl). Mask is a bool
// pipelined 2 steps ahead -> h-update is a pure FSEL. Explicit 2-step
// unroll hard-codes the ping-pong buffers. One __syncthreads per step.
// ---------------------------------------------------------------------------
__global__ void __launch_bounds__(128) rnn_kernel(
    const int* __restrict__ tokens,
    const float* __restrict__ U,
    const float* __restrict__ Wd,
    const float* __restrict__ bd,
    float* __restrict__ out)
{
    __shared__ __align__(16) float hbufA[NH];
    __shared__ __align__(16) float hbufB[NH];
    __shared__ float red[4][2];
    const int w     = threadIdx.x >> 5;
    const int l     = threadIdx.x & 31;
    const int j     = w * 16 + (l & 15);
    const int kbase = (l >> 4) * 32;
    const bool low  = (l < 16);
    const int b     = blockIdx.x;

    // U[kbase..kbase+31][j] in 32 registers.
    float Ucol[NH / 2];
    #pragma unroll
    for (int k = 0; k < NH / 2; k++)
        Ucol[k] = U[(kbase + k) * NH + j];

    if (threadIdx.x < NH) hbufA[threadIdx.x] = 0.f;
    __syncthreads();

    const int* trow = tokens + b * NT;
    float h = 0.f, s = 0.f;

    // Pipeline at entry of step T: tk = trow[T+2]; ew_cur/ew_nxt = EW rows
    // for T/T+1; m_cur/m_nxt = masks for T/T+1. ew loads have 2 full steps
    // (> L2 ~234cyc) to land; mask/ew selects resolve off the critical path.
    int   t0 = trow[0], t1 = trow[1];
    int   tk = trow[2];
    float ew_cur = g_EWb[t0 * NH + j];
    float ew_nxt = g_EWb[t1 * NH + j];
    bool  m_cur = (t0 != 0), m_nxt = (t1 != 0);

    #define RNN_STEP(SRC, DST, T)                                             \
    {                                                                         \
        float ew_new = g_EWb[tk * NH + j];     /* EW row for step T+2 */      \
        int   t3 = (T) + 3; if (t3 >= NT) t3 = NT - 1;                        \
        int   tk_new = trow[t3];                                              \
        const float4* hp = reinterpret_cast<const float4*>((SRC) + kbase);    \
        float4 h0 = hp[0], h1 = hp[1], h2 = hp[2], h3 = hp[3];                \
        float4 h4 = hp[4], h5 = hp[5], h6 = hp[6], h7 = hp[7];                \
        float a0 = low ? ew_cur : 0.f;                                        \
        float a1 = 0.f, a2 = 0.f, a3 = 0.f;                                   \
        float a4 = 0.f, a5 = 0.f, a6 = 0.f, a7 = 0.f;                         \
        a0 = fmaf(h0.x, Ucol[0],  a0);  a1 = fmaf(h0.y, Ucol[1],  a1);        \
        a2 = fmaf(h0.z, Ucol[2],  a2);  a3 = fmaf(h0.w, Ucol[3],  a3);        \
        a4 = fmaf(h1.x, Ucol[4],  a4);  a5 = fmaf(h1.y, Ucol[5],  a5);        \
        a6 = fmaf(h1.z, Ucol[6],  a6);  a7 = fmaf(h1.w, Ucol[7],  a7);        \
        a0 = fmaf(h2.x, Ucol[8],  a0);  a1 = fmaf(h2.y, Ucol[9],  a1);        \
        a2 = fmaf(h2.z, Ucol[10], a2);  a3 = fmaf(h2.w, Ucol[11], a3);        \
        a4 = fmaf(h3.x, Ucol[12], a4);  a5 = fmaf(h3.y, Ucol[13], a5);        \
        a6 = fmaf(h3.z, Ucol[14], a6);  a7 = fmaf(h3.w, Ucol[15], a7);        \
        a0 = fmaf(h4.x, Ucol[16], a0);  a1 = fmaf(h4.y, Ucol[17], a1);        \
        a2 = fmaf(h4.z, Ucol[18], a2);  a3 = fmaf(h4.w, Ucol[19], a3);        \
        a4 = fmaf(h5.x, Ucol[20], a4);  a5 = fmaf(h5.y, Ucol[21], a5);        \
        a6 = fmaf(h5.z, Ucol[22], a6);  a7 = fmaf(h5.w, Ucol[23], a7);        \
        a0 = fmaf(h6.x, Ucol[24], a0);  a1 = fmaf(h6.y, Ucol[25], a1);        \
        a2 = fmaf(h6.z, Ucol[26], a2);  a3 = fmaf(h6.w, Ucol[27], a3);        \
        a4 = fmaf(h7.x, Ucol[28], a4);  a5 = fmaf(h7.y, Ucol[29], a5);        \
        a6 = fmaf(h7.z, Ucol[30], a6);  a7 = fmaf(h7.w, Ucol[31], a7);        \
        float p_ = ((a0 + a1) + (a2 + a3)) + ((a4 + a5) + (a6 + a7));         \
        float a_ = p_ + __shfl_xor_sync(0xffffffffu, p_, 16);                 \
        float hn = tanh_fast(a_);                                             \
        h = m_cur ? hn : h;                                                   \
        if (low) (DST)[j] = h;                                                \
        s += h;                                                               \
        m_cur = m_nxt; m_nxt = (tk != 0);                                     \
        ew_cur = ew_nxt; ew_nxt = ew_new;                                     \
        tk = tk_new;                                                          \
        __syncthreads();                                                      \
    }

    for (int t = 0; t < NT; t += 2) {
        RNN_STEP(hbufA, hbufB, t);
        RNN_STEP(hbufB, hbufA, t + 1);
    }
    #undef RNN_STEP

    // Epilogue: mean pool -> dense (64 -> 2) -> sigmoid. Output j is held by
    // 2 lanes; count only l<16.
    float p  = s * (1.0f / NT);
    float c0 = low ? p * Wd[j * NC + 0] : 0.f;
    float c1 = low ? p * Wd[j * NC + 1] : 0.f;
    #pragma unroll
    for (int off = 16; off; off >>= 1) {
        c0 += __shfl_xor_sync(0xffffffffu, c0, off);
        c1 += __shfl_xor_sync(0xffffffffu, c1, off);
    }
    if (l == 0) { red[w][0] = c0; red[w][1] = c1; }
    __syncthreads();
    if (threadIdx.x == 0) {
        float C0 = red[0][0] + red[1][0] + red[2][0] + red[3][0] + bd[0];
        float C1 = red[0][1] + red[1][1] + red[2][1] + red[3][1] + bd[1];
        out[b * NC + 0] = 1.0f / (1.0f + expf(-C0));
        out[b * NC + 1] = 1.0f / (1.0f + expf(-C1));
    }
}

// ---------------------------------------------------------------------------
extern "C" void kernel_launch(void* const* d_in, const int* in_sizes, int n_in,
                              void* d_out, int out_size) {
    const int*   tokens = (const int*)  d_in[0];
    const float* E      = (const float*)d_in[1];
    const float* W      = (const float*)d_in[2];
    const float* U      = (const float*)d_in[3];
    const float* bias   = (const float*)d_in[4];
    const float* Wd     = (const float*)d_in[5];
    const float* bd     = (const float*)d_in[6];
    float* out = (float*)d_out;

    ew_kernel<<<(NV + 3) / 4, 256>>>(E, W, bias);
    rnn_kernel<<<NB, 128>>>(tokens, U, Wd, bd, out);
}

// round 7
// speedup vs baseline: 1.1557x; 1.1557x over previous
#include <cuda_runtime.h>

#define NB 256
#define NT 1024
#define NV 5000
#define ND 100
#define NH 64
#define NC 2

// Scratch: EW = E @ W + b, [V, H]. 1.28 MB -> fully L2-resident.
__device__ float g_EWb[NV * NH];

// ---------------------------------------------------------------------------
// Kernel A: EWb[v][j] = sum_d E[v][d] * W[d][j] + b[j]
// ---------------------------------------------------------------------------
__global__ void ew_kernel(const float* __restrict__ E,
                          const float* __restrict__ W,
                          const float* __restrict__ bias) {
    int v = blockIdx.x * 4 + (threadIdx.x >> 6);
    int j = threadIdx.x & 63;
    if (v >= NV) return;
    float acc = bias[j];
    const float* e = E + v * ND;
    #pragma unroll 4
    for (int d = 0; d < ND; d++)
        acc = fmaf(e[d], W[d * NH + j], acc);
    g_EWb[v * NH + j] = acc;
}

// HW tanh (MUFU.TANH): lat 16, single instruction, ~2^-11 error.
__device__ __forceinline__ float tanh_fast(float x) {
    float y;
    asm("tanh.approx.f32 %0, %1;" : "=f"(y) : "f"(x));
    return y;
}

// ---------------------------------------------------------------------------
// Kernel B: masked tanh RNN, T=1024 steps + mean-pool + dense + sigmoid.
// ONE BLOCK (256 threads = 8 warps) PER ROW. K-SPLIT BY 4 IN-WARP: lane
// quartet (l, l+8, l+16, l+24) of warp w owns output j = 8w + (l&7);
// lane's K-quarter = (l>>3)*16. Per thread: 16 scalar FFMA + 4 LDS.128.
// Quadrant partials merge with THREE INDEPENDENT shfl.xor (8,16,24) that
// all read the original partial (overlapped latency, no bfly chain).
// ew is folded into the kbase==0 quadrant's accumulator, so every lane
// inherits it through the merge. Loop structure kept verbatim from the
// best (R4) kernel: pragma-unroll-2 ping-pong on t&1, scheduled by ptxas.
// ---------------------------------------------------------------------------
__global__ void __launch_bounds__(256) rnn_kernel(
    const int* __restrict__ tokens,
    const float* __restrict__ U,
    const float* __restrict__ Wd,
    const float* __restrict__ bd,
    float* __restrict__ out)
{
    __shared__ __align__(16) float hbuf[2][NH];
    __shared__ float red[8][2];
    const int w     = threadIdx.x >> 5;
    const int l     = threadIdx.x & 31;
    const int j     = w * 8 + (l & 7);   // owned output index
    const int kbase = (l >> 3) * 16;     // this lane's K-quarter
    const bool k0   = (l < 8);           // quadrant that carries ew
    const int b     = blockIdx.x;

    // U[kbase..kbase+15][j] in 16 registers.
    float Ucol[NH / 4];
    #pragma unroll
    for (int k = 0; k < NH / 4; k++)
        Ucol[k] = U[(kbase + k) * NH + j];

    if (threadIdx.x < NH) hbuf[0][threadIdx.x] = 0.f;
    __syncthreads();

    const int* trow = tokens + b * NT;
    float h = 0.f, s = 0.f;

    // Pipeline: tokens 3 ahead, EW rows 2 ahead (2 steps >= L2 ~234cyc).
    int tok0 = trow[0];
    int tok1 = trow[1];
    int tok2 = trow[2];
    float ew0 = g_EWb[tok0 * NH + j];
    float ew1 = g_EWb[tok1 * NH + j];

    #pragma unroll 2
    for (int t = 0; t < NT; t++) {
        int t3 = (t + 3 < NT) ? (t + 3) : (NT - 1);
        int tok3 = trow[t3];
        float ew2 = g_EWb[tok2 * NH + j];

        // Partial dot over this lane's K-quarter; 4 broadcast LDS.128.
        const float4* hp = reinterpret_cast<const float4*>(hbuf[t & 1] + kbase);
        float4 h0 = hp[0], h1 = hp[1], h2 = hp[2], h3 = hp[3];
        float a0 = k0 ? ew0 : 0.f;
        float a1 = 0.f, a2 = 0.f, a3 = 0.f;
        a0 = fmaf(h0.x, Ucol[0],  a0);  a1 = fmaf(h0.y, Ucol[1],  a1);
        a2 = fmaf(h0.z, Ucol[2],  a2);  a3 = fmaf(h0.w, Ucol[3],  a3);
        a0 = fmaf(h1.x, Ucol[4],  a0);  a1 = fmaf(h1.y, Ucol[5],  a1);
        a2 = fmaf(h1.z, Ucol[6],  a2);  a3 = fmaf(h1.w, Ucol[7],  a3);
        a0 = fmaf(h2.x, Ucol[8],  a0);  a1 = fmaf(h2.y, Ucol[9],  a1);
        a2 = fmaf(h2.z, Ucol[10], a2);  a3 = fmaf(h2.w, Ucol[11], a3);
        a0 = fmaf(h3.x, Ucol[12], a0);  a1 = fmaf(h3.y, Ucol[13], a1);
        a2 = fmaf(h3.z, Ucol[14], a2);  a3 = fmaf(h3.w, Ucol[15], a3);
        float p = (a0 + a1) + (a2 + a3);
        // Merge 4 K-quadrants: 3 independent shfls of the ORIGINAL p.
        float q8  = __shfl_xor_sync(0xffffffffu, p, 8);
        float q16 = __shfl_xor_sync(0xffffffffu, p, 16);
        float q24 = __shfl_xor_sync(0xffffffffu, p, 24);
        float a = (p + q8) + (q16 + q24);
        float hn = tanh_fast(a);

        // Masked recurrence: token 0 carries previous state (block-uniform).
        if (tok0 != 0) h = hn;
        s += h;

        // Publish into the other buffer (one writer per output).
        if (k0) hbuf[(t & 1) ^ 1][j] = h;
        __syncthreads();

        tok0 = tok1; tok1 = tok2; tok2 = tok3;
        ew0 = ew1;  ew1 = ew2;
    }

    // Epilogue: mean pool -> dense (64 -> 2) -> sigmoid.
    // Output j is held by 4 lanes; count only the kbase==0 quadrant.
    float p  = s * (1.0f / NT);
    float c0 = k0 ? p * Wd[j * NC + 0] : 0.f;
    float c1 = k0 ? p * Wd[j * NC + 1] : 0.f;
    #pragma unroll
    for (int off = 16; off; off >>= 1) {
        c0 += __shfl_xor_sync(0xffffffffu, c0, off);
        c1 += __shfl_xor_sync(0xffffffffu, c1, off);
    }
    if (l == 0) { red[w][0] = c0; red[w][1] = c1; }
    __syncthreads();
    if (threadIdx.x == 0) {
        float C0 = bd[0], C1 = bd[1];
        #pragma unroll
        for (int q = 0; q < 8; q++) { C0 += red[q][0]; C1 += red[q][1]; }
        out[b * NC + 0] = 1.0f / (1.0f + expf(-C0));
        out[b * NC + 1] = 1.0f / (1.0f + expf(-C1));
    }
}

// ---------------------------------------------------------------------------
extern "C" void kernel_launch(void* const* d_in, const int* in_sizes, int n_in,
                              void* d_out, int out_size) {
    const int*   tokens = (const int*)  d_in[0];
    const float* E      = (const float*)d_in[1];
    const float* W      = (const float*)d_in[2];
    const float* U      = (const float*)d_in[3];
    const float* bias   = (const float*)d_in[4];
    const float* Wd     = (const float*)d_in[5];
    const float* bd     = (const float*)d_in[6];
    float* out = (float*)d_out;

    ew_kernel<<<(NV + 3) / 4, 256>>>(E, W, bias);
    rnn_kernel<<<NB, 256>>>(tokens, U, Wd, bd, out);
}